// round 4
// baseline (speedup 1.0000x reference)
#include <cuda_runtime.h>
#include <cuda_bf16.h>
#include <cstdint>

// B=8, L=4096, D=1024, ALPHA=64. Rows R = 32768.
// out = mask * ( softmax(x @ M + bias) @ C_V^T ),  M = W_Q^T C_K / 32, bias = b_Q C_K / 32
// computed as: out = mask * ( cmean + (A - 1/64) @ C_V^T ),  cmean[d] = (1/64) sum_a C_V[d][a]

#define SPX 72                      // fp32 smem row stride (pad 64->72)
#define SPB 72                      // bf16 smem row stride
#define XS_HALF (128 * SPX)         // floats per x buffer
#define BS_HALF (64 * SPB)          // bf16 per M buffer
#define CV_HALF (128 * SPB)         // bf16 per C_V buffer
#define XS_BYTES (2 * XS_HALF * 4)  // 73728
#define BS_BYTES (2 * BS_HALF * 2)  // 18432
#define SMEM_MAIN (XS_BYTES + BS_BYTES + 64 * 4)  // 92416

// ---------------- device scratch (no allocations allowed) ----------------
__device__ float          g_Mpart[16 * 64 * 1024];
__device__ float          g_biaspart[16 * 64];
__device__ __nv_bfloat16  g_MT[64 * 1024];    // M^T [a][d], includes 1/32
__device__ __nv_bfloat16  g_CVbf[1024 * 64];  // C_V bf16 [d][a]
__device__ float          g_cmean[1024];
__device__ float          g_bias[64];

// ---------------- helpers ----------------
__device__ __forceinline__ uint32_t f2bf2(float lo, float hi) {
    uint32_t r;
    asm("cvt.rn.bf16x2.f32 %0, %1, %2;" : "=r"(r) : "f"(hi), "f"(lo));
    return r;
}
__device__ __forceinline__ void mma16816(float* c, uint32_t a0, uint32_t a1,
                                         uint32_t a2, uint32_t a3,
                                         uint32_t b0, uint32_t b1) {
    asm volatile(
        "mma.sync.aligned.m16n8k16.row.col.f32.bf16.bf16.f32 "
        "{%0,%1,%2,%3},{%4,%5,%6,%7},{%8,%9},{%0,%1,%2,%3};"
        : "+f"(c[0]), "+f"(c[1]), "+f"(c[2]), "+f"(c[3])
        : "r"(a0), "r"(a1), "r"(a2), "r"(a3), "r"(b0), "r"(b1));
}
__device__ __forceinline__ void cp16(void* d, const void* s) {
    uint32_t a = (uint32_t)__cvta_generic_to_shared(d);
    asm volatile("cp.async.cg.shared.global [%0], [%1], 16;" :: "r"(a), "l"(s));
}
#define CP_COMMIT  asm volatile("cp.async.commit_group;" ::: "memory")
#define CP_WAIT(n) asm volatile("cp.async.wait_group %0;" :: "n"(n) : "memory")

// ========== prep1: split-K partials of M[d][a] = sum_e W_Q[e][d] C_K[e][a] ==========
// grid 256 = 16 d-tiles x 16 e-slices, block 256
__global__ void prep1_kernel(const float* __restrict__ W_Q,
                             const float* __restrict__ C_K,
                             const float* __restrict__ b_Q) {
    __shared__ float Wq_s[64 * 64];   // [e][d]
    __shared__ float Ck_s[64 * 64];   // [e][a]
    __shared__ float bq_s[64];
    const int tid = threadIdx.x;
    const int bd = blockIdx.x & 15, sl = blockIdx.x >> 4;
    const int d0 = bd * 64, e0 = sl * 64;
#pragma unroll
    for (int i = 0; i < 4; i++) {
        int idx = tid + i * 256;
        int row = idx >> 4, c = (idx & 15) << 2;
        *(float4*)&Wq_s[row * 64 + c] = *(const float4*)&W_Q[(size_t)(e0 + row) * 1024 + d0 + c];
        *(float4*)&Ck_s[row * 64 + c] = *(const float4*)&C_K[(size_t)(e0 + row) * 64 + c];
    }
    if (tid < 64) bq_s[tid] = b_Q[e0 + tid];
    __syncthreads();

    const int aq = (tid & 15) * 4;
    const int dq = (tid >> 4) * 4;
    float acc[4][4] = {};
#pragma unroll 4
    for (int e = 0; e < 64; e++) {
        float4 cv = *(const float4*)&Ck_s[e * 64 + aq];
        float4 wv = *(const float4*)&Wq_s[e * 64 + dq];
        float ca[4] = {cv.x, cv.y, cv.z, cv.w};
        float wa[4] = {wv.x, wv.y, wv.z, wv.w};
#pragma unroll
        for (int ai = 0; ai < 4; ai++)
#pragma unroll
            for (int dj = 0; dj < 4; dj++) acc[ai][dj] += ca[ai] * wa[dj];
    }
#pragma unroll
    for (int ai = 0; ai < 4; ai++) {
        float4 v = make_float4(acc[ai][0], acc[ai][1], acc[ai][2], acc[ai][3]);
        *(float4*)&g_Mpart[(size_t)sl * 65536 + (size_t)(aq + ai) * 1024 + d0 + dq] = v;
    }
    if (bd == 0 && tid < 64) {
        float s = 0.f;
#pragma unroll 8
        for (int e = 0; e < 64; e++) s += bq_s[e] * Ck_s[e * 64 + tid];
        g_biaspart[sl * 64 + tid] = s;
    }
}

// ========== prep2: reduce partials, bf16 conversions, cmean, bias ==========
// grid 64, block 1024
__global__ void prep2_kernel(const float* __restrict__ C_V) {
    const int gid = blockIdx.x * 1024 + threadIdx.x;   // 0..65535
    const int a = gid >> 10, d = gid & 1023;
    float s = 0.f;
#pragma unroll
    for (int sl = 0; sl < 16; sl++) s += g_Mpart[(size_t)sl * 65536 + a * 1024 + d];
    g_MT[a * 1024 + d] = __float2bfloat16(s * 0.03125f);   // 1/sqrt(1024)
    g_CVbf[gid] = __float2bfloat16(C_V[gid]);
    if (gid < 1024) {
        float s2 = 0.f;
#pragma unroll 8
        for (int j = 0; j < 64; j++) s2 += C_V[gid * 64 + j];
        g_cmean[gid] = s2 * (1.0f / 64.0f);
    }
    if (gid < 64) {
        float s3 = 0.f;
#pragma unroll
        for (int sl = 0; sl < 16; sl++) s3 += g_biaspart[sl * 64 + gid];
        g_bias[gid] = s3 * 0.03125f;
    }
}

// ========== main fused kernel: 256 CTAs x 256 thr, 128 rows/CTA ==========
__global__ void __launch_bounds__(256, 2)
col_main(const float* __restrict__ x, const int* __restrict__ mask,
         float* __restrict__ out) {
    extern __shared__ char sm[];
    float*          xs     = (float*)sm;                          // [2][128][SPX] fp32
    __nv_bfloat16*  bsm    = (__nv_bfloat16*)(sm + XS_BYTES);     // [2][64][SPB] bf16
    float*          bias_s = (float*)(sm + XS_BYTES + BS_BYTES);  // [64]
    __nv_bfloat16*  cvs    = (__nv_bfloat16*)sm;                  // overlays xs in GEMM2

    const int tid = threadIdx.x;
    const int w = tid >> 5, lane = tid & 31;
    const int rg = lane >> 2, tig = lane & 3;    // mma groupID / thread-in-group
    const int wr = w * 16;
    const int row0 = blockIdx.x * 128;

    if (tid < 64) bias_s[tid] = g_bias[tid];
    const float m0 = (mask[row0 + wr + rg] != 0) ? 1.0f : 0.0f;
    const float m1 = (mask[row0 + wr + rg + 8] != 0) ? 1.0f : 0.0f;

    auto issueX = [&](int kc, int buf) {
        float* dst = xs + buf * XS_HALF;
        const float* src = x + (size_t)row0 * 1024 + kc * 64;
#pragma unroll
        for (int i = 0; i < 8; i++) {
            int idx = tid + i * 256;
            int r = idx >> 4, c = (idx & 15) << 2;
            cp16(dst + r * SPX + c, src + (size_t)r * 1024 + c);
        }
    };
    auto issueB = [&](int kc, int buf) {
        __nv_bfloat16* dst = bsm + buf * BS_HALF;
        const __nv_bfloat16* src = g_MT + kc * 64;
#pragma unroll
        for (int i = 0; i < 2; i++) {
            int idx = tid + i * 256;
            int r = idx >> 3, c = (idx & 7) << 3;
            cp16(dst + r * SPB + c, src + r * 1024 + c);
        }
    };
    auto issueCV = [&](int nc, int buf) {
        __nv_bfloat16* dst = cvs + buf * CV_HALF;
        const __nv_bfloat16* src = g_CVbf + nc * 128 * 64;
#pragma unroll
        for (int i = 0; i < 4; i++) {
            int idx = tid + i * 256;
            int r = idx >> 3, c = (idx & 7) << 3;
            cp16(dst + r * SPB + c, src + r * 64 + c);
        }
    };

    // -------- GEMM1: logits[128][64] = x @ M  (warp: 16 rows x 64 cols) --------
    float acc[8][4];
#pragma unroll
    for (int nt = 0; nt < 8; nt++)
        acc[nt][0] = acc[nt][1] = acc[nt][2] = acc[nt][3] = 0.f;

    issueX(0, 0); issueB(0, 0); CP_COMMIT;
    issueX(1, 1); issueB(1, 1); CP_COMMIT;

    for (int kc = 0; kc < 16; kc++) {
        CP_WAIT(1);
        __syncthreads();
        const int buf = kc & 1;
        const float* xb = xs + buf * XS_HALF;
        const __nv_bfloat16* bb = bsm + buf * BS_HALF;
#pragma unroll
        for (int ks = 0; ks < 4; ks++) {
            const int k2 = ks * 16 + 2 * tig;
            float2 f0 = *(const float2*)(xb + (wr + rg) * SPX + k2);
            float2 f1 = *(const float2*)(xb + (wr + rg + 8) * SPX + k2);
            float2 f2 = *(const float2*)(xb + (wr + rg) * SPX + k2 + 8);
            float2 f3 = *(const float2*)(xb + (wr + rg + 8) * SPX + k2 + 8);
            uint32_t a0 = f2bf2(f0.x, f0.y), a1 = f2bf2(f1.x, f1.y);
            uint32_t a2 = f2bf2(f2.x, f2.y), a3 = f2bf2(f3.x, f3.y);
#pragma unroll
            for (int nt = 0; nt < 8; nt++) {
                uint32_t b0 = *(const uint32_t*)(bb + (nt * 8 + rg) * SPB + k2);
                uint32_t b1 = *(const uint32_t*)(bb + (nt * 8 + rg) * SPB + k2 + 8);
                mma16816(acc[nt], a0, a1, a2, a3, b0, b1);
            }
        }
        __syncthreads();
        if (kc + 2 < 16) { issueX(kc + 2, buf); issueB(kc + 2, buf); }
        CP_COMMIT;
    }
    CP_WAIT(0);
    __syncthreads();

    // start C_V prefetch (overlaps softmax)
    issueCV(0, 0); CP_COMMIT;
    issueCV(1, 1); CP_COMMIT;

    // -------- softmax, fully in registers (rows rg and rg+8 of this warp) --------
#pragma unroll
    for (int nt = 0; nt < 8; nt++) {
        float b0v = bias_s[nt * 8 + 2 * tig], b1v = bias_s[nt * 8 + 2 * tig + 1];
        acc[nt][0] += b0v; acc[nt][1] += b1v; acc[nt][2] += b0v; acc[nt][3] += b1v;
    }
    float mx0 = -1e30f, mx1 = -1e30f;
#pragma unroll
    for (int nt = 0; nt < 8; nt++) {
        mx0 = fmaxf(mx0, fmaxf(acc[nt][0], acc[nt][1]));
        mx1 = fmaxf(mx1, fmaxf(acc[nt][2], acc[nt][3]));
    }
    mx0 = fmaxf(mx0, __shfl_xor_sync(0xffffffffu, mx0, 1));
    mx0 = fmaxf(mx0, __shfl_xor_sync(0xffffffffu, mx0, 2));
    mx1 = fmaxf(mx1, __shfl_xor_sync(0xffffffffu, mx1, 1));
    mx1 = fmaxf(mx1, __shfl_xor_sync(0xffffffffu, mx1, 2));
    float s0 = 0.f, s1 = 0.f;
#pragma unroll
    for (int nt = 0; nt < 8; nt++) {
        acc[nt][0] = __expf(acc[nt][0] - mx0); s0 += acc[nt][0];
        acc[nt][1] = __expf(acc[nt][1] - mx0); s0 += acc[nt][1];
        acc[nt][2] = __expf(acc[nt][2] - mx1); s1 += acc[nt][2];
        acc[nt][3] = __expf(acc[nt][3] - mx1); s1 += acc[nt][3];
    }
    s0 += __shfl_xor_sync(0xffffffffu, s0, 1);
    s0 += __shfl_xor_sync(0xffffffffu, s0, 2);
    s1 += __shfl_xor_sync(0xffffffffu, s1, 1);
    s1 += __shfl_xor_sync(0xffffffffu, s1, 2);
    const float i0 = 1.0f / s0, i1 = 1.0f / s1, cC = 1.0f / 64.0f;

    // GEMM1 C-layout == GEMM2 A-fragment layout: pack directly, no smem round-trip
    uint32_t af[4][4];
#pragma unroll
    for (int kt = 0; kt < 4; kt++) {
        af[kt][0] = f2bf2(acc[2 * kt][0] * i0 - cC,     acc[2 * kt][1] * i0 - cC);
        af[kt][1] = f2bf2(acc[2 * kt][2] * i1 - cC,     acc[2 * kt][3] * i1 - cC);
        af[kt][2] = f2bf2(acc[2 * kt + 1][0] * i0 - cC, acc[2 * kt + 1][1] * i0 - cC);
        af[kt][3] = f2bf2(acc[2 * kt + 1][2] * i1 - cC, acc[2 * kt + 1][3] * i1 - cC);
    }

    // -------- GEMM2: out[128][1024] = Acent @ C_V^T, streamed in 128-col chunks --------
    for (int nc = 0; nc < 8; nc++) {
        CP_WAIT(1);
        __syncthreads();
        const __nv_bfloat16* cb = cvs + (nc & 1) * CV_HALF;
        float a2c[16][4];
#pragma unroll
        for (int nt = 0; nt < 16; nt++)
            a2c[nt][0] = a2c[nt][1] = a2c[nt][2] = a2c[nt][3] = 0.f;
#pragma unroll
        for (int kt = 0; kt < 4; kt++) {
#pragma unroll
            for (int nt = 0; nt < 16; nt++) {
                uint32_t b0 = *(const uint32_t*)(cb + (nt * 8 + rg) * SPB + kt * 16 + 2 * tig);
                uint32_t b1 = *(const uint32_t*)(cb + (nt * 8 + rg) * SPB + kt * 16 + 2 * tig + 8);
                mma16816(a2c[nt], af[kt][0], af[kt][1], af[kt][2], af[kt][3], b0, b1);
            }
        }
        const size_t r0 = (size_t)(row0 + wr + rg) * 1024;
#pragma unroll
        for (int nt = 0; nt < 16; nt++) {
            int col = nc * 128 + nt * 8 + 2 * tig;
            float2 cm = *(const float2*)(g_cmean + col);
            float2 o0 = make_float2(m0 * (a2c[nt][0] + cm.x), m0 * (a2c[nt][1] + cm.y));
            float2 o1 = make_float2(m1 * (a2c[nt][2] + cm.x), m1 * (a2c[nt][3] + cm.y));
            *(float2*)(out + r0 + col) = o0;
            *(float2*)(out + r0 + 8 * 1024 + col) = o1;
        }
        __syncthreads();
        if (nc + 2 < 8) issueCV(nc + 2, nc & 1);
        CP_COMMIT;
    }
}

// ---------------- launch ----------------
extern "C" void kernel_launch(void* const* d_in, const int* in_sizes, int n_in,
                              void* d_out, int out_size) {
    const float* x    = (const float*)d_in[0];
    const int*   mask = (const int*)d_in[1];
    const float* W_Q  = (const float*)d_in[2];
    const float* b_Q  = (const float*)d_in[3];
    const float* C_K  = (const float*)d_in[4];
    const float* C_V  = (const float*)d_in[5];
    float*       out  = (float*)d_out;

    cudaFuncSetAttribute(col_main, cudaFuncAttributeMaxDynamicSharedMemorySize, SMEM_MAIN);

    prep1_kernel<<<256, 256>>>(W_Q, C_K, b_Q);
    prep2_kernel<<<64, 1024>>>(C_V);
    col_main<<<256, 256, SMEM_MAIN>>>(x, mask, out);
}

// round 7
// speedup vs baseline: 1.0963x; 1.0963x over previous
#include <cuda_runtime.h>
#include <cuda_bf16.h>
#include <cstdint>

// B=8, L=4096, D=1024, ALPHA=64. Rows R = 32768.
// out = mask * ( softmax(x @ M + bias) @ C_V^T ),  M = W_Q^T C_K / 32, bias = b_Q C_K / 32
// computed as: out = mask * ( cmean + (A - 1/64) @ C_V^T ),  cmean[d] = (1/64) sum_a C_V[d][a]
//
// Main kernel: zero smem, zero __syncthreads. x streamed via direct LDG;
// M and C_V pre-packed into mma.m16n8k16 B-fragment order (L1/L2-hot LDG.64).

// ---------------- device scratch (no allocations allowed) ----------------
__device__ float g_Mpart[32 * 64 * 1024];     // [slice][a][d] fp32 partials (8 MB)
__device__ float g_biaspart[32 * 64];
__device__ uint2 g_Mfrag[64 * 8 * 32];        // [ki][nt][lane] = {b0,b1} bf16x2 pairs
__device__ uint2 g_CVfrag[8 * 4 * 16 * 32];   // [nc][kt][nt][lane]
__device__ float g_cmean[1024];
__device__ float g_bias[64];

// ---------------- helpers ----------------
__device__ __forceinline__ uint32_t f2bf2(float lo, float hi) {
    uint32_t r;
    asm("cvt.rn.bf16x2.f32 %0, %1, %2;" : "=r"(r) : "f"(hi), "f"(lo));
    return r;
}
__device__ __forceinline__ void mma16816(float* c, uint32_t a0, uint32_t a1,
                                         uint32_t a2, uint32_t a3,
                                         uint32_t b0, uint32_t b1) {
    asm volatile(
        "mma.sync.aligned.m16n8k16.row.col.f32.bf16.bf16.f32 "
        "{%0,%1,%2,%3},{%4,%5,%6,%7},{%8,%9},{%0,%1,%2,%3};"
        : "+f"(c[0]), "+f"(c[1]), "+f"(c[2]), "+f"(c[3])
        : "r"(a0), "r"(a1), "r"(a2), "r"(a3), "r"(b0), "r"(b1));
}

// ========== prep1: split-K partials of M[a][d] = sum_e W_Q[e][d] C_K[e][a] ==========
// grid 512 = 16 d-tiles x 32 e-slices, block 256
__global__ void prep1_kernel(const float* __restrict__ W_Q,
                             const float* __restrict__ C_K,
                             const float* __restrict__ b_Q) {
    __shared__ float Wq_s[32 * 64];   // [e][d]
    __shared__ float Ck_s[32 * 64];   // [e][a]
    __shared__ float bq_s[32];
    const int tid = threadIdx.x;
    const int bd = blockIdx.x & 15, sl = blockIdx.x >> 4;   // sl 0..31
    const int d0 = bd * 64, e0 = sl * 32;
#pragma unroll
    for (int i = 0; i < 2; i++) {
        int idx = tid + i * 256;
        int row = idx >> 4, c = (idx & 15) << 2;
        *(float4*)&Wq_s[row * 64 + c] = *(const float4*)&W_Q[(size_t)(e0 + row) * 1024 + d0 + c];
        *(float4*)&Ck_s[row * 64 + c] = *(const float4*)&C_K[(size_t)(e0 + row) * 64 + c];
    }
    if (tid < 32) bq_s[tid] = b_Q[e0 + tid];
    __syncthreads();

    const int aq = (tid & 15) * 4;
    const int dq = (tid >> 4) * 4;
    float acc[4][4] = {};
#pragma unroll 4
    for (int e = 0; e < 32; e++) {
        float4 cv = *(const float4*)&Ck_s[e * 64 + aq];
        float4 wv = *(const float4*)&Wq_s[e * 64 + dq];
        float ca[4] = {cv.x, cv.y, cv.z, cv.w};
        float wa[4] = {wv.x, wv.y, wv.z, wv.w};
#pragma unroll
        for (int ai = 0; ai < 4; ai++)
#pragma unroll
            for (int dj = 0; dj < 4; dj++) acc[ai][dj] += ca[ai] * wa[dj];
    }
#pragma unroll
    for (int ai = 0; ai < 4; ai++) {
        float4 v = make_float4(acc[ai][0], acc[ai][1], acc[ai][2], acc[ai][3]);
        *(float4*)&g_Mpart[(size_t)sl * 65536 + (size_t)(aq + ai) * 1024 + d0 + dq] = v;
    }
    if (bd == 0 && tid < 64) {
        float s = 0.f;
#pragma unroll
        for (int e = 0; e < 32; e++) s += bq_s[e] * Ck_s[e * 64 + tid];
        g_biaspart[sl * 64 + tid] = s;
    }
}

// ========== prep2: pack C_V fragments + cmean (independent of prep1) ==========
// grid 64 x 256 = 16384 threads, one per CVfrag uint2
__global__ void prep2_kernel(const float* __restrict__ C_V) {
    const int fid = blockIdx.x * 256 + threadIdx.x;      // 0..16383
    const int nc = fid >> 11, kt = (fid >> 9) & 3, nt = (fid >> 5) & 15, lane = fid & 31;
    const int rg = lane >> 2, tig = lane & 3;
    const int n = nc * 128 + nt * 8 + rg;                // d index 0..1023
    const int k2 = kt * 16 + 2 * tig;                    // a index
    const float* cvr = C_V + (size_t)n * 64;
    uint2 v;
    v.x = f2bf2(cvr[k2],     cvr[k2 + 1]);
    v.y = f2bf2(cvr[k2 + 8], cvr[k2 + 9]);
    g_CVfrag[fid] = v;

    if (fid < 1024) {
        float s2 = 0.f;
        const float* r = C_V + (size_t)fid * 64;
#pragma unroll 8
        for (int j = 0; j < 64; j++) s2 += r[j];
        g_cmean[fid] = s2 * (1.0f / 64.0f);
    }
}

// ========== prep3: reduce M partials -> Mfrag, reduce bias ==========
// grid 64 x 256 = 16384 threads, one per Mfrag uint2
__global__ void prep3_kernel() {
    const int fid = blockIdx.x * 256 + threadIdx.x;      // 0..16383
    const int ki = fid >> 8, nt = (fid >> 5) & 7, lane = fid & 31;
    const int rg = lane >> 2, tig = lane & 3;
    const int n = nt * 8 + rg;                            // a index 0..63
    const int k2 = ki * 16 + 2 * tig;                     // d index
    float m[4] = {0.f, 0.f, 0.f, 0.f};
    const int koff[4] = {k2, k2 + 1, k2 + 8, k2 + 9};
#pragma unroll 4
    for (int sl = 0; sl < 32; sl++) {
        const float* p = g_Mpart + (size_t)sl * 65536 + (size_t)n * 1024;
#pragma unroll
        for (int j = 0; j < 4; j++) m[j] += p[koff[j]];
    }
    uint2 v;
    v.x = f2bf2(m[0] * 0.03125f, m[1] * 0.03125f);
    v.y = f2bf2(m[2] * 0.03125f, m[3] * 0.03125f);
    g_Mfrag[fid] = v;

    if (fid < 64) {
        float s = 0.f;
#pragma unroll
        for (int sl = 0; sl < 32; sl++) s += g_biaspart[sl * 64 + fid];
        g_bias[fid] = s * 0.03125f;
    }
}

// ========== main: 256 CTAs x 256 thr, 128 rows/CTA, NO smem / NO barriers ==========
__global__ void __launch_bounds__(256, 2)
col_main(const float* __restrict__ x, const int* __restrict__ mask,
         float* __restrict__ out) {
    const int tid = threadIdx.x;
    const int w = tid >> 5, lane = tid & 31;
    const int rg = lane >> 2, tig = lane & 3;
    const int row0 = blockIdx.x * 128;
    const int r0 = row0 + w * 16 + rg;            // first mma row of this thread
    const float m0 = (mask[r0] != 0) ? 1.0f : 0.0f;
    const float m1 = (mask[r0 + 8] != 0) ? 1.0f : 0.0f;

    // -------- GEMM1: logits[16rows x 64] per warp, 64 k16-steps, direct LDG --------
    const float* xr0 = x + (size_t)r0 * 1024 + 2 * tig;
    const float* xr1 = xr0 + (size_t)8 * 1024;
    const uint2* mf = g_Mfrag + lane;

    float acc[8][4];
#pragma unroll
    for (int nt = 0; nt < 8; nt++)
        acc[nt][0] = acc[nt][1] = acc[nt][2] = acc[nt][3] = 0.f;

#pragma unroll 4
    for (int ki = 0; ki < 64; ki++) {
        const int k0 = ki * 16;
        float2 f0 = *(const float2*)(xr0 + k0);
        float2 f1 = *(const float2*)(xr1 + k0);
        float2 f2 = *(const float2*)(xr0 + k0 + 8);
        float2 f3 = *(const float2*)(xr1 + k0 + 8);
        uint32_t a0 = f2bf2(f0.x, f0.y), a1 = f2bf2(f1.x, f1.y);
        uint32_t a2 = f2bf2(f2.x, f2.y), a3 = f2bf2(f3.x, f3.y);
#pragma unroll
        for (int nt = 0; nt < 8; nt++) {
            uint2 b = mf[(ki * 8 + nt) << 5];
            mma16816(acc[nt], a0, a1, a2, a3, b.x, b.y);
        }
    }

    // -------- softmax, fully in registers --------
#pragma unroll
    for (int nt = 0; nt < 8; nt++) {
        float2 bv = *(const float2*)&g_bias[nt * 8 + 2 * tig];
        acc[nt][0] += bv.x; acc[nt][1] += bv.y; acc[nt][2] += bv.x; acc[nt][3] += bv.y;
    }
    float mx0 = -1e30f, mx1 = -1e30f;
#pragma unroll
    for (int nt = 0; nt < 8; nt++) {
        mx0 = fmaxf(mx0, fmaxf(acc[nt][0], acc[nt][1]));
        mx1 = fmaxf(mx1, fmaxf(acc[nt][2], acc[nt][3]));
    }
    mx0 = fmaxf(mx0, __shfl_xor_sync(0xffffffffu, mx0, 1));
    mx0 = fmaxf(mx0, __shfl_xor_sync(0xffffffffu, mx0, 2));
    mx1 = fmaxf(mx1, __shfl_xor_sync(0xffffffffu, mx1, 1));
    mx1 = fmaxf(mx1, __shfl_xor_sync(0xffffffffu, mx1, 2));
    float s0 = 0.f, s1 = 0.f;
#pragma unroll
    for (int nt = 0; nt < 8; nt++) {
        acc[nt][0] = __expf(acc[nt][0] - mx0); s0 += acc[nt][0];
        acc[nt][1] = __expf(acc[nt][1] - mx0); s0 += acc[nt][1];
        acc[nt][2] = __expf(acc[nt][2] - mx1); s1 += acc[nt][2];
        acc[nt][3] = __expf(acc[nt][3] - mx1); s1 += acc[nt][3];
    }
    s0 += __shfl_xor_sync(0xffffffffu, s0, 1);
    s0 += __shfl_xor_sync(0xffffffffu, s0, 2);
    s1 += __shfl_xor_sync(0xffffffffu, s1, 1);
    s1 += __shfl_xor_sync(0xffffffffu, s1, 2);
    const float i0 = 1.0f / s0, i1 = 1.0f / s1, cC = 1.0f / 64.0f;

    // GEMM1 C-layout == GEMM2 A-fragment layout: pack directly
    uint32_t af[4][4];
#pragma unroll
    for (int kt = 0; kt < 4; kt++) {
        af[kt][0] = f2bf2(acc[2 * kt][0] * i0 - cC,     acc[2 * kt][1] * i0 - cC);
        af[kt][1] = f2bf2(acc[2 * kt][2] * i1 - cC,     acc[2 * kt][3] * i1 - cC);
        af[kt][2] = f2bf2(acc[2 * kt + 1][0] * i0 - cC, acc[2 * kt + 1][1] * i0 - cC);
        af[kt][3] = f2bf2(acc[2 * kt + 1][2] * i1 - cC, acc[2 * kt + 1][3] * i1 - cC);
    }

    // -------- GEMM2: out[.][1024] = Acent @ C_V^T, 8 chunks of 128 cols --------
    const uint2* cvf = g_CVfrag + lane;
    float* out0 = out + (size_t)r0 * 1024 + 2 * tig;
    float* out1 = out0 + (size_t)8 * 1024;

#pragma unroll 1
    for (int nc = 0; nc < 8; nc++) {
        float a2c[16][4];
#pragma unroll
        for (int nt = 0; nt < 16; nt++)
            a2c[nt][0] = a2c[nt][1] = a2c[nt][2] = a2c[nt][3] = 0.f;
#pragma unroll
        for (int kt = 0; kt < 4; kt++) {
#pragma unroll
            for (int nt = 0; nt < 16; nt++) {
                uint2 b = cvf[(((nc << 2) + kt) * 16 + nt) << 5];
                mma16816(a2c[nt], af[kt][0], af[kt][1], af[kt][2], af[kt][3], b.x, b.y);
            }
        }
#pragma unroll
        for (int nt = 0; nt < 16; nt++) {
            int col = nc * 128 + nt * 8;     // +2*tig folded into out0/out1
            float2 cm = *(const float2*)(g_cmean + col + 2 * tig);
            float2 o0 = make_float2(m0 * (a2c[nt][0] + cm.x), m0 * (a2c[nt][1] + cm.y));
            float2 o1 = make_float2(m1 * (a2c[nt][2] + cm.x), m1 * (a2c[nt][3] + cm.y));
            *(float2*)(out0 + col) = o0;
            *(float2*)(out1 + col) = o1;
        }
    }
}

// ---------------- launch ----------------
extern "C" void kernel_launch(void* const* d_in, const int* in_sizes, int n_in,
                              void* d_out, int out_size) {
    const float* x    = (const float*)d_in[0];
    const int*   mask = (const int*)d_in[1];
    const float* W_Q  = (const float*)d_in[2];
    const float* b_Q  = (const float*)d_in[3];
    const float* C_K  = (const float*)d_in[4];
    const float* C_V  = (const float*)d_in[5];
    float*       out  = (float*)d_out;

    prep1_kernel<<<512, 256>>>(W_Q, C_K, b_Q);
    prep2_kernel<<<64, 256>>>(C_V);
    prep3_kernel<<<64, 256>>>();
    col_main<<<256, 256>>>(x, mask, out);
}

// round 11
// speedup vs baseline: 1.1182x; 1.0199x over previous
#include <cuda_runtime.h>
#include <cuda_bf16.h>
#include <cstdint>

// B=8, L=4096, D=1024, ALPHA=64. Rows R = 32768.
// out = mask * ( softmax(x @ M + bias) @ C_V^T ),  M = W_Q^T C_K / 32, bias = b_Q C_K / 32
// computed as: out = mask * ( cmean + (A - 1/64) @ C_V^T )
//
// Main: grid 128 x 512 thr, 256 rows/CTA, 1 CTA/SM. Phased smem: Mfrag ->
// GEMM1 -> CVfrag (same buffer) -> GEMM2. Output staged in smem for STG.128.

#define FRAG_BYTES 131072                  // 16384 uint2
#define OSTRIDE    72                      // fp32 out-stage row stride
#define OUT_BYTES  (256 * OSTRIDE * 4)     // 73728
#define SMEM_MAIN  (FRAG_BYTES + OUT_BYTES)// 204800

// ---------------- device scratch ----------------
__device__ float g_Mpart[32 * 64 * 1024];
__device__ float g_biaspart[32 * 64];
__device__ uint2 g_Mfrag[64 * 8 * 32];       // [ki][nt][lane]
__device__ uint2 g_CVfrag[16 * 4 * 8 * 32];  // [nc][kt][nt][lane]
__device__ float g_cmean[1024];
__device__ float g_bias[64];

// ---------------- helpers ----------------
__device__ __forceinline__ uint32_t f2bf2(float lo, float hi) {
    uint32_t r;
    asm("cvt.rn.bf16x2.f32 %0, %1, %2;" : "=r"(r) : "f"(hi), "f"(lo));
    return r;
}
__device__ __forceinline__ void mma16816(float* c, uint32_t a0, uint32_t a1,
                                         uint32_t a2, uint32_t a3,
                                         uint32_t b0, uint32_t b1) {
    asm volatile(
        "mma.sync.aligned.m16n8k16.row.col.f32.bf16.bf16.f32 "
        "{%0,%1,%2,%3},{%4,%5,%6,%7},{%8,%9},{%0,%1,%2,%3};"
        : "+f"(c[0]), "+f"(c[1]), "+f"(c[2]), "+f"(c[3])
        : "r"(a0), "r"(a1), "r"(a2), "r"(a3), "r"(b0), "r"(b1));
}
__device__ __forceinline__ void cp16(void* d, const void* s) {
    uint32_t a = (uint32_t)__cvta_generic_to_shared(d);
    asm volatile("cp.async.cg.shared.global [%0], [%1], 16;" :: "r"(a), "l"(s));
}
#define CP_COMMIT  asm volatile("cp.async.commit_group;" ::: "memory")
#define CP_WAIT0   asm volatile("cp.async.wait_group 0;" ::: "memory")

// ========== prep1: split-K partials of M[a][d], 32 slices x 16 d-tiles ==========
__global__ void prep1_kernel(const float* __restrict__ W_Q,
                             const float* __restrict__ C_K,
                             const float* __restrict__ b_Q) {
    __shared__ float Wq_s[32 * 64];
    __shared__ float Ck_s[32 * 64];
    __shared__ float bq_s[32];
    const int tid = threadIdx.x;
    const int bd = blockIdx.x & 15, sl = blockIdx.x >> 4;
    const int d0 = bd * 64, e0 = sl * 32;
#pragma unroll
    for (int i = 0; i < 2; i++) {
        int idx = tid + i * 256;
        int row = idx >> 4, c = (idx & 15) << 2;
        *(float4*)&Wq_s[row * 64 + c] = *(const float4*)&W_Q[(size_t)(e0 + row) * 1024 + d0 + c];
        *(float4*)&Ck_s[row * 64 + c] = *(const float4*)&C_K[(size_t)(e0 + row) * 64 + c];
    }
    if (tid < 32) bq_s[tid] = b_Q[e0 + tid];
    __syncthreads();

    const int aq = (tid & 15) * 4;
    const int dq = (tid >> 4) * 4;
    float acc[4][4] = {};
#pragma unroll 4
    for (int e = 0; e < 32; e++) {
        float4 cv = *(const float4*)&Ck_s[e * 64 + aq];
        float4 wv = *(const float4*)&Wq_s[e * 64 + dq];
        float ca[4] = {cv.x, cv.y, cv.z, cv.w};
        float wa[4] = {wv.x, wv.y, wv.z, wv.w};
#pragma unroll
        for (int ai = 0; ai < 4; ai++)
#pragma unroll
            for (int dj = 0; dj < 4; dj++) acc[ai][dj] += ca[ai] * wa[dj];
    }
#pragma unroll
    for (int ai = 0; ai < 4; ai++) {
        float4 v = make_float4(acc[ai][0], acc[ai][1], acc[ai][2], acc[ai][3]);
        *(float4*)&g_Mpart[(size_t)sl * 65536 + (size_t)(aq + ai) * 1024 + d0 + dq] = v;
    }
    if (bd == 0 && tid < 64) {
        float s = 0.f;
#pragma unroll
        for (int e = 0; e < 32; e++) s += bq_s[e] * Ck_s[e * 64 + tid];
        g_biaspart[sl * 64 + tid] = s;
    }
}

// ========== prep23: Mfrag reduce + bias | CVfrag pack + cmean ==========
// grid 128 x 256 = 32768 threads
__global__ void prep23_kernel(const float* __restrict__ C_V) {
    const int id = blockIdx.x * 256 + threadIdx.x;
    if (id < 16384) {
        const int ki = id >> 8, nt = (id >> 5) & 7, lane = id & 31;
        const int rg = lane >> 2, tig = lane & 3;
        const int n = nt * 8 + rg;
        const int k2 = ki * 16 + 2 * tig;
        float m[4] = {0.f, 0.f, 0.f, 0.f};
#pragma unroll 4
        for (int sl = 0; sl < 32; sl++) {
            const float* p = g_Mpart + (size_t)sl * 65536 + (size_t)n * 1024;
            m[0] += p[k2]; m[1] += p[k2 + 1]; m[2] += p[k2 + 8]; m[3] += p[k2 + 9];
        }
        uint2 v;
        v.x = f2bf2(m[0] * 0.03125f, m[1] * 0.03125f);
        v.y = f2bf2(m[2] * 0.03125f, m[3] * 0.03125f);
        g_Mfrag[id] = v;
        if (id < 64) {
            float s = 0.f;
#pragma unroll
            for (int sl = 0; sl < 32; sl++) s += g_biaspart[sl * 64 + id];
            g_bias[id] = s * 0.03125f;
        }
    } else {
        const int f = id - 16384;
        const int lane = f & 31, nt = (f >> 5) & 7, kt = (f >> 8) & 3, nc = f >> 10;
        const int rg = lane >> 2, tig = lane & 3;
        const int n = nc * 64 + nt * 8 + rg;
        const int k2 = kt * 16 + 2 * tig;
        const float* r = C_V + (size_t)n * 64;
        uint2 v;
        v.x = f2bf2(r[k2],     r[k2 + 1]);
        v.y = f2bf2(r[k2 + 8], r[k2 + 9]);
        g_CVfrag[f] = v;
        if (f < 1024) {
            float s2 = 0.f;
            const float* cr = C_V + (size_t)f * 64;
#pragma unroll 8
            for (int j = 0; j < 64; j++) s2 += cr[j];
            g_cmean[f] = s2 * (1.0f / 64.0f);
        }
    }
}

// ========== main: grid 128 x 512 thr, 256 rows/CTA, phased smem ==========
__global__ void __launch_bounds__(512, 1)
col_main(const float* __restrict__ x, const int* __restrict__ mask,
         float* __restrict__ out) {
    extern __shared__ char sm[];
    uint2* frag = (uint2*)sm;                       // Mfrag then CVfrag (reused)
    float* outs = (float*)(sm + FRAG_BYTES);        // [256][OSTRIDE]

    const int tid = threadIdx.x;
    const int w = tid >> 5, lane = tid & 31;
    const int rg = lane >> 2, tig = lane & 3;
    const int wr = w * 16;
    const int row0g = blockIdx.x * 256;
    const int r0 = row0g + wr + rg;

    // ---- fill Mfrag into smem ----
    {
        const char* src = (const char*)g_Mfrag;
#pragma unroll
        for (int i = 0; i < 16; i++) {
            int o = (tid + i * 512) * 16;
            cp16(sm + o, src + o);
        }
        CP_COMMIT;
    }
    // mask values for the store phase: row = i*32 + (tid>>4), fixed per thread
    float mst[8];
#pragma unroll
    for (int i = 0; i < 8; i++)
        mst[i] = (mask[row0g + i * 32 + (tid >> 4)] != 0) ? 1.0f : 0.0f;

    CP_WAIT0;
    __syncthreads();

    // ---- GEMM1: logits = x @ M  (x via float4 + quad shuffles, B via LDS) ----
    float acc[8][4];
#pragma unroll
    for (int nt = 0; nt < 8; nt++)
        acc[nt][0] = acc[nt][1] = acc[nt][2] = acc[nt][3] = 0.f;

    const float* xr0 = x + (size_t)r0 * 1024 + 4 * tig;
    const float* xr1 = xr0 + (size_t)8 * 1024;
    const uint2* mf = frag + lane;
    const int s0 = (lane & ~3) | (tig >> 1), s1 = s0 + 2;
    const bool hi = (tig & 1);

#pragma unroll 2
    for (int ki = 0; ki < 64; ki++) {
        float4 qa = *(const float4*)(xr0 + ki * 16);
        float4 qb = *(const float4*)(xr1 + ki * 16);
        uint32_t loA = f2bf2(qa.x, qa.y), hiA = f2bf2(qa.z, qa.w);
        uint32_t loB = f2bf2(qb.x, qb.y), hiB = f2bf2(qb.z, qb.w);
        uint32_t t0l = __shfl_sync(0xffffffffu, loA, s0), t0h = __shfl_sync(0xffffffffu, hiA, s0);
        uint32_t t1l = __shfl_sync(0xffffffffu, loB, s0), t1h = __shfl_sync(0xffffffffu, hiB, s0);
        uint32_t t2l = __shfl_sync(0xffffffffu, loA, s1), t2h = __shfl_sync(0xffffffffu, hiA, s1);
        uint32_t t3l = __shfl_sync(0xffffffffu, loB, s1), t3h = __shfl_sync(0xffffffffu, hiB, s1);
        uint32_t a0 = hi ? t0h : t0l, a1 = hi ? t1h : t1l;
        uint32_t a2 = hi ? t2h : t2l, a3 = hi ? t3h : t3l;
#pragma unroll
        for (int nt = 0; nt < 8; nt++) {
            uint2 b = mf[(ki * 8 + nt) << 5];
            mma16816(acc[nt], a0, a1, a2, a3, b.x, b.y);
        }
    }
    __syncthreads();   // all warps done reading Mfrag

    // ---- fill CVfrag over the same smem (overlaps softmax) ----
    {
        const char* src = (const char*)g_CVfrag;
#pragma unroll
        for (int i = 0; i < 16; i++) {
            int o = (tid + i * 512) * 16;
            cp16(sm + o, src + o);
        }
        CP_COMMIT;
    }

    // ---- softmax in registers ----
#pragma unroll
    for (int nt = 0; nt < 8; nt++) {
        float2 bv = *(const float2*)&g_bias[nt * 8 + 2 * tig];
        acc[nt][0] += bv.x; acc[nt][1] += bv.y; acc[nt][2] += bv.x; acc[nt][3] += bv.y;
    }
    float mx0 = -1e30f, mx1 = -1e30f;
#pragma unroll
    for (int nt = 0; nt < 8; nt++) {
        mx0 = fmaxf(mx0, fmaxf(acc[nt][0], acc[nt][1]));
        mx1 = fmaxf(mx1, fmaxf(acc[nt][2], acc[nt][3]));
    }
    mx0 = fmaxf(mx0, __shfl_xor_sync(0xffffffffu, mx0, 1));
    mx0 = fmaxf(mx0, __shfl_xor_sync(0xffffffffu, mx0, 2));
    mx1 = fmaxf(mx1, __shfl_xor_sync(0xffffffffu, mx1, 1));
    mx1 = fmaxf(mx1, __shfl_xor_sync(0xffffffffu, mx1, 2));
    float sm0 = 0.f, sm1 = 0.f;
#pragma unroll
    for (int nt = 0; nt < 8; nt++) {
        acc[nt][0] = __expf(acc[nt][0] - mx0); sm0 += acc[nt][0];
        acc[nt][1] = __expf(acc[nt][1] - mx0); sm0 += acc[nt][1];
        acc[nt][2] = __expf(acc[nt][2] - mx1); sm1 += acc[nt][2];
        acc[nt][3] = __expf(acc[nt][3] - mx1); sm1 += acc[nt][3];
    }
    sm0 += __shfl_xor_sync(0xffffffffu, sm0, 1);
    sm0 += __shfl_xor_sync(0xffffffffu, sm0, 2);
    sm1 += __shfl_xor_sync(0xffffffffu, sm1, 1);
    sm1 += __shfl_xor_sync(0xffffffffu, sm1, 2);
    const float i0 = 1.0f / sm0, i1 = 1.0f / sm1, cC = 1.0f / 64.0f;

    uint32_t af[4][4];
#pragma unroll
    for (int kt = 0; kt < 4; kt++) {
        af[kt][0] = f2bf2(acc[2 * kt][0] * i0 - cC,     acc[2 * kt][1] * i0 - cC);
        af[kt][1] = f2bf2(acc[2 * kt][2] * i1 - cC,     acc[2 * kt][3] * i1 - cC);
        af[kt][2] = f2bf2(acc[2 * kt + 1][0] * i0 - cC, acc[2 * kt + 1][1] * i0 - cC);
        af[kt][3] = f2bf2(acc[2 * kt + 1][2] * i1 - cC, acc[2 * kt + 1][3] * i1 - cC);
    }

    CP_WAIT0;
    __syncthreads();   // CVfrag ready

    // ---- GEMM2: 16 chunks of 64 cols, staged stores ----
    const uint2* cvf = frag + lane;
    const int c4 = (tid & 15) * 4;
    const int srow = tid >> 4;

    for (int nc = 0; nc < 16; nc++) {
        float a2c[8][4];
#pragma unroll
        for (int nt = 0; nt < 8; nt++)
            a2c[nt][0] = a2c[nt][1] = a2c[nt][2] = a2c[nt][3] = 0.f;
#pragma unroll
        for (int kt = 0; kt < 4; kt++) {
#pragma unroll
            for (int nt = 0; nt < 8; nt++) {
                uint2 b = cvf[((((nc << 2) + kt) << 3) + nt) << 5];
                mma16816(a2c[nt], af[kt][0], af[kt][1], af[kt][2], af[kt][3], b.x, b.y);
            }
        }
        __syncthreads();   // previous chunk's store-phase reads complete
#pragma unroll
        for (int nt = 0; nt < 8; nt++) {
            int c = nt * 8 + 2 * tig;
            *(float2*)&outs[(wr + rg) * OSTRIDE + c]     = make_float2(a2c[nt][0], a2c[nt][1]);
            *(float2*)&outs[(wr + rg + 8) * OSTRIDE + c] = make_float2(a2c[nt][2], a2c[nt][3]);
        }
        __syncthreads();   // staging complete
        const int c0 = nc * 64;
        float4 cm = *(const float4*)(g_cmean + c0 + c4);
#pragma unroll
        for (int i = 0; i < 8; i++) {
            int row = i * 32 + srow;
            float4 v = *(const float4*)&outs[row * OSTRIDE + c4];
            float m = mst[i];
            float4 o = make_float4(m * (v.x + cm.x), m * (v.y + cm.y),
                                   m * (v.z + cm.z), m * (v.w + cm.w));
            *(float4*)(out + (size_t)(row0g + row) * 1024 + c0 + c4) = o;
        }
    }
}

// ---------------- launch ----------------
extern "C" void kernel_launch(void* const* d_in, const int* in_sizes, int n_in,
                              void* d_out, int out_size) {
    const float* x    = (const float*)d_in[0];
    const int*   mask = (const int*)d_in[1];
    const float* W_Q  = (const float*)d_in[2];
    const float* b_Q  = (const float*)d_in[3];
    const float* C_K  = (const float*)d_in[4];
    const float* C_V  = (const float*)d_in[5];
    float*       out  = (float*)d_out;

    cudaFuncSetAttribute(col_main, cudaFuncAttributeMaxDynamicSharedMemorySize, SMEM_MAIN);

    prep1_kernel<<<512, 256>>>(W_Q, C_K, b_Q);
    prep23_kernel<<<128, 256>>>(C_V);
    col_main<<<128, 512, SMEM_MAIN>>>(x, mask, out);
}

// round 12
// speedup vs baseline: 1.3529x; 1.2099x over previous
#include <cuda_runtime.h>
#include <cuda_bf16.h>
#include <cstdint>

// B=8, L=4096, D=1024, ALPHA=64. Rows R = 32768.
// out = mask * ( softmax(x @ M + bias) @ C_V^T ),  M = W_Q^T C_K / 32, bias = b_Q C_K / 32
// computed as: out = mask * ( cmean + (A - 1/64) @ C_V^T )
//
// Main kernel: barrier-free, no smem. x via LDG.128 (k-permuted mma slots, no
// shuffles). M / C_V pre-packed in mma B-fragment order, L1-hot (streams use
// .cs hints to avoid thrashing them).

// ---------------- device scratch ----------------
__device__ float g_Mpart[32 * 64 * 1024];
__device__ float g_biaspart[32 * 64];
__device__ uint2 g_Mfrag[64 * 8 * 32];       // [ki][nt][lane], k-slots permuted: {4t,4t+1,4t+2,4t+3}
__device__ uint2 g_CVfrag[16 * 4 * 8 * 32];  // [nc][kt][nt][lane], standard slots
__device__ float g_cmean[1024];
__device__ float g_bias[64];

// ---------------- helpers ----------------
__device__ __forceinline__ uint32_t f2bf2(float lo, float hi) {
    uint32_t r;
    asm("cvt.rn.bf16x2.f32 %0, %1, %2;" : "=r"(r) : "f"(hi), "f"(lo));
    return r;
}
__device__ __forceinline__ void mma16816(float* c, uint32_t a0, uint32_t a1,
                                         uint32_t a2, uint32_t a3,
                                         uint32_t b0, uint32_t b1) {
    asm volatile(
        "mma.sync.aligned.m16n8k16.row.col.f32.bf16.bf16.f32 "
        "{%0,%1,%2,%3},{%4,%5,%6,%7},{%8,%9},{%0,%1,%2,%3};"
        : "+f"(c[0]), "+f"(c[1]), "+f"(c[2]), "+f"(c[3])
        : "r"(a0), "r"(a1), "r"(a2), "r"(a3), "r"(b0), "r"(b1));
}

// ========== prep1: split-K partials of M[a][d], 32 slices x 16 d-tiles ==========
__global__ void prep1_kernel(const float* __restrict__ W_Q,
                             const float* __restrict__ C_K,
                             const float* __restrict__ b_Q) {
    __shared__ float Wq_s[32 * 64];
    __shared__ float Ck_s[32 * 64];
    __shared__ float bq_s[32];
    const int tid = threadIdx.x;
    const int bd = blockIdx.x & 15, sl = blockIdx.x >> 4;
    const int d0 = bd * 64, e0 = sl * 32;
#pragma unroll
    for (int i = 0; i < 2; i++) {
        int idx = tid + i * 256;
        int row = idx >> 4, c = (idx & 15) << 2;
        *(float4*)&Wq_s[row * 64 + c] = *(const float4*)&W_Q[(size_t)(e0 + row) * 1024 + d0 + c];
        *(float4*)&Ck_s[row * 64 + c] = *(const float4*)&C_K[(size_t)(e0 + row) * 64 + c];
    }
    if (tid < 32) bq_s[tid] = b_Q[e0 + tid];
    __syncthreads();

    const int aq = (tid & 15) * 4;
    const int dq = (tid >> 4) * 4;
    float acc[4][4] = {};
#pragma unroll 4
    for (int e = 0; e < 32; e++) {
        float4 cv = *(const float4*)&Ck_s[e * 64 + aq];
        float4 wv = *(const float4*)&Wq_s[e * 64 + dq];
        float ca[4] = {cv.x, cv.y, cv.z, cv.w};
        float wa[4] = {wv.x, wv.y, wv.z, wv.w};
#pragma unroll
        for (int ai = 0; ai < 4; ai++)
#pragma unroll
            for (int dj = 0; dj < 4; dj++) acc[ai][dj] += ca[ai] * wa[dj];
    }
#pragma unroll
    for (int ai = 0; ai < 4; ai++) {
        float4 v = make_float4(acc[ai][0], acc[ai][1], acc[ai][2], acc[ai][3]);
        *(float4*)&g_Mpart[(size_t)sl * 65536 + (size_t)(aq + ai) * 1024 + d0 + dq] = v;
    }
    if (bd == 0 && tid < 64) {
        float s = 0.f;
#pragma unroll
        for (int e = 0; e < 32; e++) s += bq_s[e] * Ck_s[e * 64 + tid];
        g_biaspart[sl * 64 + tid] = s;
    }
}

// ========== prep23: Mfrag reduce (k-permuted) + bias | CVfrag pack + cmean ==========
// grid 128 x 256 = 32768 threads
__global__ void prep23_kernel(const float* __restrict__ C_V) {
    const int id = blockIdx.x * 256 + threadIdx.x;
    if (id < 16384) {
        // Mfrag: lane tig supplies k-slots {4t,4t+1,4t+2,4t+3} (permuted to match
        // contiguous float4 x loads in the main kernel's A fragment).
        const int ki = id >> 8, nt = (id >> 5) & 7, lane = id & 31;
        const int rg = lane >> 2, tig = lane & 3;
        const int n = nt * 8 + rg;
        const int k4 = ki * 16 + 4 * tig;
        float4 m = make_float4(0.f, 0.f, 0.f, 0.f);
#pragma unroll 4
        for (int sl = 0; sl < 32; sl++) {
            float4 p = *(const float4*)(g_Mpart + (size_t)sl * 65536 + (size_t)n * 1024 + k4);
            m.x += p.x; m.y += p.y; m.z += p.z; m.w += p.w;
        }
        uint2 v;
        v.x = f2bf2(m.x * 0.03125f, m.y * 0.03125f);
        v.y = f2bf2(m.z * 0.03125f, m.w * 0.03125f);
        g_Mfrag[id] = v;
        if (id < 64) {
            float s = 0.f;
#pragma unroll
            for (int sl = 0; sl < 32; sl++) s += g_biaspart[sl * 64 + id];
            g_bias[id] = s * 0.03125f;
        }
    } else {
        // CVfrag: standard B-fragment slots {2t,2t+1} / {2t+8,2t+9}
        const int f = id - 16384;
        const int lane = f & 31, nt = (f >> 5) & 7, kt = (f >> 8) & 3, nc = f >> 10;
        const int rg = lane >> 2, tig = lane & 3;
        const int n = nc * 64 + nt * 8 + rg;
        const int k2 = kt * 16 + 2 * tig;
        const float* r = C_V + (size_t)n * 64;
        uint2 v;
        v.x = f2bf2(r[k2],     r[k2 + 1]);
        v.y = f2bf2(r[k2 + 8], r[k2 + 9]);
        g_CVfrag[f] = v;
        if (f < 1024) {
            float s2 = 0.f;
            const float* cr = C_V + (size_t)f * 64;
#pragma unroll 8
            for (int j = 0; j < 64; j++) s2 += cr[j];
            g_cmean[f] = s2 * (1.0f / 64.0f);
        }
    }
}

// ========== main: 256 CTAs x 256 thr, 128 rows/CTA, barrier-free ==========
__global__ void __launch_bounds__(256, 2)
col_main(const float* __restrict__ x, const int* __restrict__ mask,
         float* __restrict__ out) {
    const int tid = threadIdx.x;
    const int w = tid >> 5, lane = tid & 31;
    const int rg = lane >> 2, tig = lane & 3;
    const int r0 = blockIdx.x * 128 + w * 16 + rg;
    const float m0 = (mask[r0] != 0) ? 1.0f : 0.0f;
    const float m1 = (mask[r0 + 8] != 0) ? 1.0f : 0.0f;

    // -------- GEMM1: logits = x @ M. x via contiguous LDG.128 (k-permuted slots) --------
    const float* xr0 = x + (size_t)r0 * 1024 + 4 * tig;
    const float* xr1 = xr0 + (size_t)8 * 1024;
    const uint2* mf = g_Mfrag + lane;

    float acc[8][4];
#pragma unroll
    for (int nt = 0; nt < 8; nt++)
        acc[nt][0] = acc[nt][1] = acc[nt][2] = acc[nt][3] = 0.f;

#pragma unroll 4
    for (int ki = 0; ki < 64; ki++) {
        float4 qa = __ldcs((const float4*)(xr0 + ki * 16));   // rows rg
        float4 qb = __ldcs((const float4*)(xr1 + ki * 16));   // rows rg+8
        uint32_t a0 = f2bf2(qa.x, qa.y), a2 = f2bf2(qa.z, qa.w);
        uint32_t a1 = f2bf2(qb.x, qb.y), a3 = f2bf2(qb.z, qb.w);
#pragma unroll
        for (int nt = 0; nt < 8; nt++) {
            uint2 b = mf[(ki * 8 + nt) << 5];
            mma16816(acc[nt], a0, a1, a2, a3, b.x, b.y);
        }
    }

    // -------- softmax, fully in registers --------
#pragma unroll
    for (int nt = 0; nt < 8; nt++) {
        float2 bv = *(const float2*)&g_bias[nt * 8 + 2 * tig];
        acc[nt][0] += bv.x; acc[nt][1] += bv.y; acc[nt][2] += bv.x; acc[nt][3] += bv.y;
    }
    float mx0 = -1e30f, mx1 = -1e30f;
#pragma unroll
    for (int nt = 0; nt < 8; nt++) {
        mx0 = fmaxf(mx0, fmaxf(acc[nt][0], acc[nt][1]));
        mx1 = fmaxf(mx1, fmaxf(acc[nt][2], acc[nt][3]));
    }
    mx0 = fmaxf(mx0, __shfl_xor_sync(0xffffffffu, mx0, 1));
    mx0 = fmaxf(mx0, __shfl_xor_sync(0xffffffffu, mx0, 2));
    mx1 = fmaxf(mx1, __shfl_xor_sync(0xffffffffu, mx1, 1));
    mx1 = fmaxf(mx1, __shfl_xor_sync(0xffffffffu, mx1, 2));
    float s0 = 0.f, s1 = 0.f;
#pragma unroll
    for (int nt = 0; nt < 8; nt++) {
        acc[nt][0] = __expf(acc[nt][0] - mx0); s0 += acc[nt][0];
        acc[nt][1] = __expf(acc[nt][1] - mx0); s0 += acc[nt][1];
        acc[nt][2] = __expf(acc[nt][2] - mx1); s1 += acc[nt][2];
        acc[nt][3] = __expf(acc[nt][3] - mx1); s1 += acc[nt][3];
    }
    s0 += __shfl_xor_sync(0xffffffffu, s0, 1);
    s0 += __shfl_xor_sync(0xffffffffu, s0, 2);
    s1 += __shfl_xor_sync(0xffffffffu, s1, 1);
    s1 += __shfl_xor_sync(0xffffffffu, s1, 2);
    const float i0 = 1.0f / s0, i1 = 1.0f / s1, cC = 1.0f / 64.0f;

    // GEMM1 C-layout == GEMM2 A-fragment layout (standard slots): pack directly
    uint32_t af[4][4];
#pragma unroll
    for (int kt = 0; kt < 4; kt++) {
        af[kt][0] = f2bf2(acc[2 * kt][0] * i0 - cC,     acc[2 * kt][1] * i0 - cC);
        af[kt][1] = f2bf2(acc[2 * kt][2] * i1 - cC,     acc[2 * kt][3] * i1 - cC);
        af[kt][2] = f2bf2(acc[2 * kt + 1][0] * i0 - cC, acc[2 * kt + 1][1] * i0 - cC);
        af[kt][3] = f2bf2(acc[2 * kt + 1][2] * i1 - cC, acc[2 * kt + 1][3] * i1 - cC);
    }

    // -------- GEMM2: out = Acent @ C_V^T, 16 chunks of 64 cols --------
    const uint2* cvf = g_CVfrag + lane;
    float* out0 = out + (size_t)r0 * 1024 + 2 * tig;
    float* out1 = out0 + (size_t)8 * 1024;

#pragma unroll 1
    for (int nc = 0; nc < 16; nc++) {
        float a2c[8][4];
#pragma unroll
        for (int nt = 0; nt < 8; nt++)
            a2c[nt][0] = a2c[nt][1] = a2c[nt][2] = a2c[nt][3] = 0.f;
#pragma unroll
        for (int kt = 0; kt < 4; kt++) {
#pragma unroll
            for (int nt = 0; nt < 8; nt++) {
                uint2 b = cvf[((((nc << 2) + kt) << 3) + nt) << 5];
                mma16816(a2c[nt], af[kt][0], af[kt][1], af[kt][2], af[kt][3], b.x, b.y);
            }
        }
#pragma unroll
        for (int nt = 0; nt < 8; nt++) {
            int col = nc * 64 + nt * 8;
            float2 cm = *(const float2*)(g_cmean + col + 2 * tig);
            __stcs((float2*)(out0 + col),
                   make_float2(m0 * (a2c[nt][0] + cm.x), m0 * (a2c[nt][1] + cm.y)));
            __stcs((float2*)(out1 + col),
                   make_float2(m1 * (a2c[nt][2] + cm.x), m1 * (a2c[nt][3] + cm.y)));
        }
    }
}

// ---------------- launch ----------------
extern "C" void kernel_launch(void* const* d_in, const int* in_sizes, int n_in,
                              void* d_out, int out_size) {
    const float* x    = (const float*)d_in[0];
    const int*   mask = (const int*)d_in[1];
    const float* W_Q  = (const float*)d_in[2];
    const float* b_Q  = (const float*)d_in[3];
    const float* C_K  = (const float*)d_in[4];
    const float* C_V  = (const float*)d_in[5];
    float*       out  = (float*)d_out;

    prep1_kernel<<<512, 256>>>(W_Q, C_K, b_Q);
    prep23_kernel<<<128, 256>>>(C_V);
    col_main<<<256, 256>>>(x, mask, out);
}

// round 13
// speedup vs baseline: 1.4321x; 1.0585x over previous
#include <cuda_runtime.h>
#include <cuda_bf16.h>
#include <cstdint>

// B=8, L=4096, D=1024, ALPHA=64. Rows R = 32768.
// out = mask * ( softmax(x @ M + bias) @ C_V^T ),  M = W_Q^T C_K / 32, bias = b_Q C_K / 32
// computed as: out = mask * ( cmean + (A - 1/64) @ C_V^T )
//
// Main kernel: barrier-free, no smem. x via LDG.128 (k-permuted mma slots).
// GEMM2 columns n-permuted pairwise so the epilogue writes STG.128.
// M / C_V pre-packed in mma B-fragment order, L1-hot (.cs hints on streams).

// ---------------- device scratch ----------------
__device__ float g_Mpart4[4 * 64 * 1024];    // [es][a][d] fp32 partials (1 MB)
__device__ float g_biaspart4[4 * 64];
__device__ uint2 g_Mfrag[64 * 8 * 32];       // [ki][nt][lane], k-slots {4t..4t+3}
__device__ uint2 g_CVfrag[16 * 4 * 8 * 32];  // [nc][kt][nt][lane], n-permuted pairwise
__device__ float g_cmean[1024];
__device__ float g_bias[64];

// ---------------- helpers ----------------
__device__ __forceinline__ uint32_t f2bf2(float lo, float hi) {
    uint32_t r;
    asm("cvt.rn.bf16x2.f32 %0, %1, %2;" : "=r"(r) : "f"(hi), "f"(lo));
    return r;
}
__device__ __forceinline__ void mma16816(float* c, uint32_t a0, uint32_t a1,
                                         uint32_t a2, uint32_t a3,
                                         uint32_t b0, uint32_t b1) {
    asm volatile(
        "mma.sync.aligned.m16n8k16.row.col.f32.bf16.bf16.f32 "
        "{%0,%1,%2,%3},{%4,%5,%6,%7},{%8,%9},{%0,%1,%2,%3};"
        : "+f"(c[0]), "+f"(c[1]), "+f"(c[2]), "+f"(c[3])
        : "r"(a0), "r"(a1), "r"(a2), "r"(a3), "r"(b0), "r"(b1));
}
__device__ __forceinline__ void cp16(void* d, const void* s) {
    uint32_t a = (uint32_t)__cvta_generic_to_shared(d);
    asm volatile("cp.async.cg.shared.global [%0], [%1], 16;" :: "r"(a), "l"(s));
}
#define CP_COMMIT  asm volatile("cp.async.commit_group;" ::: "memory")
#define CP_WAIT0   asm volatile("cp.async.wait_group 0;" ::: "memory")

// ========== prep1: grid 256 = 64 ki x 4 e-slices; full 256-e reduce in CTA ==========
// smem: C_K slice [256][64] fp32 (64 KB) + W_Q strip [256][16] (16 KB) + bq [256]
#define P1_SMEM (65536 + 16384 + 1024)
__global__ void __launch_bounds__(256, 2)
prep1_kernel(const float* __restrict__ W_Q, const float* __restrict__ C_K,
             const float* __restrict__ b_Q) {
    extern __shared__ float p1s[];
    float* Ck_s = p1s;               // [256][64]
    float* Wq_s = p1s + 16384;       // [256][16]
    float* bq_s = p1s + 16384 + 4096;// [256]

    const int tid = threadIdx.x;
    const int ki = blockIdx.x & 63, es = blockIdx.x >> 6;
    const int d0 = ki * 16, e0 = es * 256;

#pragma unroll
    for (int i = 0; i < 16; i++) {               // C_K slice: 256 rows x 64
        int idx = tid + i * 256;
        int row = idx >> 4, c = (idx & 15) << 2;
        cp16(&Ck_s[row * 64 + c], &C_K[(size_t)(e0 + row) * 64 + c]);
    }
#pragma unroll
    for (int i = 0; i < 4; i++) {                // W_Q strip: 256 rows x 16
        int idx = tid + i * 256;
        int row = idx >> 2, c = (idx & 3) << 2;
        cp16(&Wq_s[row * 16 + c], &W_Q[(size_t)(e0 + row) * 1024 + d0 + c]);
    }
    if (ki == 0) bq_s[tid] = b_Q[e0 + tid];
    CP_COMMIT; CP_WAIT0;
    __syncthreads();

    const int a = tid & 63, dg = (tid >> 6) << 2;    // thread: 1 a x 4 d
    float acc0 = 0.f, acc1 = 0.f, acc2 = 0.f, acc3 = 0.f;
#pragma unroll 8
    for (int e = 0; e < 256; e++) {
        float cv = Ck_s[e * 64 + a];
        float4 wv = *(const float4*)&Wq_s[e * 16 + dg];
        acc0 += cv * wv.x; acc1 += cv * wv.y; acc2 += cv * wv.z; acc3 += cv * wv.w;
    }
    *(float4*)&g_Mpart4[((size_t)es * 64 + a) * 1024 + d0 + dg] =
        make_float4(acc0, acc1, acc2, acc3);

    if (ki == 0 && tid < 64) {
        float s = 0.f;
#pragma unroll 8
        for (int e = 0; e < 256; e++) s += bq_s[e] * Ck_s[e * 64 + tid];
        g_biaspart4[es * 64 + tid] = s;
    }
}

// ========== prep2: Mfrag reduce + bias | CVfrag pack (n-permuted) + cmean ==========
// grid 128 x 256 = 32768 threads
__global__ void prep2_kernel(const float* __restrict__ C_V) {
    const int id = blockIdx.x * 256 + threadIdx.x;
    if (id < 16384) {
        // Mfrag: lane tig supplies k-slots {4t..4t+3} (matches contiguous x float4)
        const int ki = id >> 8, nt = (id >> 5) & 7, lane = id & 31;
        const int rg = lane >> 2, tig = lane & 3;
        const int n = nt * 8 + rg;
        const int k4 = ki * 16 + 4 * tig;
        float4 m = make_float4(0.f, 0.f, 0.f, 0.f);
#pragma unroll
        for (int es = 0; es < 4; es++) {
            float4 p = *(const float4*)(g_Mpart4 + ((size_t)es * 64 + n) * 1024 + k4);
            m.x += p.x; m.y += p.y; m.z += p.z; m.w += p.w;
        }
        uint2 v;
        v.x = f2bf2(m.x * 0.03125f, m.y * 0.03125f);
        v.y = f2bf2(m.z * 0.03125f, m.w * 0.03125f);
        g_Mfrag[id] = v;
        if (id < 64) {
            float s = g_biaspart4[id] + g_biaspart4[64 + id] +
                      g_biaspart4[128 + id] + g_biaspart4[192 + id];
            g_bias[id] = s * 0.03125f;
        }
    } else {
        // CVfrag: n-permuted pairwise so GEMM2 epilogue stores float4.
        // block nt = 2*pb + b; slot rg -> logical col pb*16 + 4*(rg>>1) + 2*b + (rg&1)
        const int f = id - 16384;
        const int lane = f & 31, nt = (f >> 5) & 7, kt = (f >> 8) & 3, nc = f >> 10;
        const int rg = lane >> 2, tig = lane & 3;
        const int pb = nt >> 1, b = nt & 1;
        const int n = nc * 64 + pb * 16 + ((rg >> 1) << 2) + 2 * b + (rg & 1);
        const int k2 = kt * 16 + 2 * tig;
        const float* r = C_V + (size_t)n * 64;
        uint2 v;
        v.x = f2bf2(r[k2],     r[k2 + 1]);
        v.y = f2bf2(r[k2 + 8], r[k2 + 9]);
        g_CVfrag[f] = v;
        if (f < 1024) {
            float s2 = 0.f;
            const float* cr = C_V + (size_t)f * 64;
#pragma unroll 8
            for (int j = 0; j < 64; j++) s2 += cr[j];
            g_cmean[f] = s2 * (1.0f / 64.0f);
        }
    }
}

// ========== main: 256 CTAs x 256 thr, 128 rows/CTA, barrier-free ==========
__global__ void __launch_bounds__(256, 2)
col_main(const float* __restrict__ x, const int* __restrict__ mask,
         float* __restrict__ out) {
    const int tid = threadIdx.x;
    const int w = tid >> 5, lane = tid & 31;
    const int rg = lane >> 2, tig = lane & 3;
    const int r0 = blockIdx.x * 128 + w * 16 + rg;
    const float m0 = (mask[r0] != 0) ? 1.0f : 0.0f;
    const float m1 = (mask[r0 + 8] != 0) ? 1.0f : 0.0f;

    // -------- GEMM1: logits = x @ M. x via contiguous LDG.128 (k-permuted slots) --------
    const float* xr0 = x + (size_t)r0 * 1024 + 4 * tig;
    const float* xr1 = xr0 + (size_t)8 * 1024;
    const uint2* mf = g_Mfrag + lane;

    float acc[8][4];
#pragma unroll
    for (int nt = 0; nt < 8; nt++)
        acc[nt][0] = acc[nt][1] = acc[nt][2] = acc[nt][3] = 0.f;

#pragma unroll 4
    for (int ki = 0; ki < 64; ki++) {
        float4 qa = __ldcs((const float4*)(xr0 + ki * 16));   // rows rg
        float4 qb = __ldcs((const float4*)(xr1 + ki * 16));   // rows rg+8
        uint32_t a0 = f2bf2(qa.x, qa.y), a2 = f2bf2(qa.z, qa.w);
        uint32_t a1 = f2bf2(qb.x, qb.y), a3 = f2bf2(qb.z, qb.w);
#pragma unroll
        for (int nt = 0; nt < 8; nt++) {
            uint2 b = mf[(ki * 8 + nt) << 5];
            mma16816(acc[nt], a0, a1, a2, a3, b.x, b.y);
        }
    }

    // -------- softmax, fully in registers --------
#pragma unroll
    for (int nt = 0; nt < 8; nt++) {
        float2 bv = *(const float2*)&g_bias[nt * 8 + 2 * tig];
        acc[nt][0] += bv.x; acc[nt][1] += bv.y; acc[nt][2] += bv.x; acc[nt][3] += bv.y;
    }
    float mx0 = -1e30f, mx1 = -1e30f;
#pragma unroll
    for (int nt = 0; nt < 8; nt++) {
        mx0 = fmaxf(mx0, fmaxf(acc[nt][0], acc[nt][1]));
        mx1 = fmaxf(mx1, fmaxf(acc[nt][2], acc[nt][3]));
    }
    mx0 = fmaxf(mx0, __shfl_xor_sync(0xffffffffu, mx0, 1));
    mx0 = fmaxf(mx0, __shfl_xor_sync(0xffffffffu, mx0, 2));
    mx1 = fmaxf(mx1, __shfl_xor_sync(0xffffffffu, mx1, 1));
    mx1 = fmaxf(mx1, __shfl_xor_sync(0xffffffffu, mx1, 2));
    float s0 = 0.f, s1 = 0.f;
#pragma unroll
    for (int nt = 0; nt < 8; nt++) {
        acc[nt][0] = __expf(acc[nt][0] - mx0); s0 += acc[nt][0];
        acc[nt][1] = __expf(acc[nt][1] - mx0); s0 += acc[nt][1];
        acc[nt][2] = __expf(acc[nt][2] - mx1); s1 += acc[nt][2];
        acc[nt][3] = __expf(acc[nt][3] - mx1); s1 += acc[nt][3];
    }
    s0 += __shfl_xor_sync(0xffffffffu, s0, 1);
    s0 += __shfl_xor_sync(0xffffffffu, s0, 2);
    s1 += __shfl_xor_sync(0xffffffffu, s1, 1);
    s1 += __shfl_xor_sync(0xffffffffu, s1, 2);
    const float i0 = 1.0f / s0, i1 = 1.0f / s1, cC = 1.0f / 64.0f;

    // GEMM1 C-layout == GEMM2 A-fragment layout (standard slots): pack directly
    uint32_t af[4][4];
#pragma unroll
    for (int kt = 0; kt < 4; kt++) {
        af[kt][0] = f2bf2(acc[2 * kt][0] * i0 - cC,     acc[2 * kt][1] * i0 - cC);
        af[kt][1] = f2bf2(acc[2 * kt][2] * i1 - cC,     acc[2 * kt][3] * i1 - cC);
        af[kt][2] = f2bf2(acc[2 * kt + 1][0] * i0 - cC, acc[2 * kt + 1][1] * i0 - cC);
        af[kt][3] = f2bf2(acc[2 * kt + 1][2] * i1 - cC, acc[2 * kt + 1][3] * i1 - cC);
    }

    // -------- GEMM2: out = Acent @ C_V^T, 16 chunks of 64 cols, STG.128 epilogue --------
    const uint2* cvf = g_CVfrag + lane;
    float* out0 = out + (size_t)r0 * 1024 + 4 * tig;
    float* out1 = out0 + (size_t)8 * 1024;

#pragma unroll 1
    for (int nc = 0; nc < 16; nc++) {
        float a2c[8][4];
#pragma unroll
        for (int nt = 0; nt < 8; nt++)
            a2c[nt][0] = a2c[nt][1] = a2c[nt][2] = a2c[nt][3] = 0.f;
#pragma unroll
        for (int kt = 0; kt < 4; kt++) {
#pragma unroll
            for (int nt = 0; nt < 8; nt++) {
                uint2 b = cvf[((((nc << 2) + kt) << 3) + nt) << 5];
                mma16816(a2c[nt], af[kt][0], af[kt][1], af[kt][2], af[kt][3], b.x, b.y);
            }
        }
        // n-permutation: pair (2pb, 2pb+1) -> thread cols pb*16 + 4*tig + {0..3}
#pragma unroll
        for (int pb = 0; pb < 4; pb++) {
            int col = nc * 64 + pb * 16;          // + 4*tig folded into out0/out1
            float4 cm = *(const float4*)(g_cmean + col + 4 * tig);
            __stcs((float4*)(out0 + col),
                   make_float4(m0 * (a2c[2*pb][0]   + cm.x), m0 * (a2c[2*pb][1]   + cm.y),
                               m0 * (a2c[2*pb+1][0] + cm.z), m0 * (a2c[2*pb+1][1] + cm.w)));
            __stcs((float4*)(out1 + col),
                   make_float4(m1 * (a2c[2*pb][2]   + cm.x), m1 * (a2c[2*pb][3]   + cm.y),
                               m1 * (a2c[2*pb+1][2] + cm.z), m1 * (a2c[2*pb+1][3] + cm.w)));
        }
    }
}

// ---------------- launch ----------------
extern "C" void kernel_launch(void* const* d_in, const int* in_sizes, int n_in,
                              void* d_out, int out_size) {
    const float* x    = (const float*)d_in[0];
    const int*   mask = (const int*)d_in[1];
    const float* W_Q  = (const float*)d_in[2];
    const float* b_Q  = (const float*)d_in[3];
    const float* C_K  = (const float*)d_in[4];
    const float* C_V  = (const float*)d_in[5];
    float*       out  = (float*)d_out;

    cudaFuncSetAttribute(prep1_kernel, cudaFuncAttributeMaxDynamicSharedMemorySize, P1_SMEM);

    prep1_kernel<<<256, 256, P1_SMEM>>>(W_Q, C_K, b_Q);
    prep2_kernel<<<128, 256>>>(C_V);
    col_main<<<256, 256>>>(x, mask, out);
}